// round 10
// baseline (speedup 1.0000x reference)
#include <cuda_runtime.h>
#include <cuda_bf16.h>
#include <math.h>
#include <stdint.h>

#define BATCH 2
#define SEQ 2048
#define DMODEL 2048
#define NH 8
#define HDIM 256
#define MROWS (BATCH * SEQ)          // 4096
#define QKVW 2560                    // merged qkv width (2048 q | 256 k | 256 v)

// ---------------- fp32 scratch ----------------
static __device__ float g_qkv[MROWS * QKVW];      // merged projection output
static __device__ float g_ao[MROWS * NH * HDIM];  // attention output (fp32)
static __device__ float2 g_rope[MROWS * 128];

// ---------------- bf16 split scratch ----------------
static __device__ __nv_bfloat16 g_hid_hi[MROWS * DMODEL];
static __device__ __nv_bfloat16 g_hid_lo[MROWS * DMODEL];
static __device__ __nv_bfloat16 g_ao_hi[MROWS * DMODEL];
static __device__ __nv_bfloat16 g_ao_lo[MROWS * DMODEL];
static __device__ __nv_bfloat16 g_wqkv_hi[QKVW * DMODEL]; // [N][K]: q 0..2047, k 2048..2303, v 2304..2559
static __device__ __nv_bfloat16 g_wqkv_lo[QKVW * DMODEL];
static __device__ __nv_bfloat16 g_wo_hi[DMODEL * DMODEL];
static __device__ __nv_bfloat16 g_wo_lo[DMODEL * DMODEL];
// flash attention operands (bf16 hi/lo, post-RoPE / dense)
static __device__ __nv_bfloat16 g_qhi[MROWS * NH * HDIM];
static __device__ __nv_bfloat16 g_qlo[MROWS * NH * HDIM];
static __device__ __nv_bfloat16 g_khi[MROWS * HDIM];
static __device__ __nv_bfloat16 g_klo[MROWS * HDIM];
static __device__ __nv_bfloat16 g_vhi[MROWS * HDIM];
static __device__ __nv_bfloat16 g_vlo[MROWS * HDIM];

// ---------------------------------------------------------------------------
// Warp-MMA helpers (baseline PTX, works under compute_103)
// ---------------------------------------------------------------------------
__device__ __forceinline__ uint32_t smem_u32(const void* p) {
    uint32_t a;
    asm("{ .reg .u64 t; cvta.to.shared.u64 t, %1; cvt.u32.u64 %0, t; }"
        : "=r"(a) : "l"(p));
    return a;
}
__device__ __forceinline__ void cp16(uint32_t s, const void* g) {
    asm volatile("cp.async.ca.shared.global [%0], [%1], 16;" :: "r"(s), "l"(g));
}
__device__ __forceinline__ void cp_commit() {
    asm volatile("cp.async.commit_group;" ::: "memory");
}
__device__ __forceinline__ void ldsm4(uint32_t* r, uint32_t a) {
    asm volatile("ldmatrix.sync.aligned.m8n8.x4.shared.b16 {%0,%1,%2,%3}, [%4];"
                 : "=r"(r[0]), "=r"(r[1]), "=r"(r[2]), "=r"(r[3]) : "r"(a));
}
__device__ __forceinline__ void ldsm4t(uint32_t* r, uint32_t a) {
    asm volatile("ldmatrix.sync.aligned.m8n8.x4.trans.shared.b16 {%0,%1,%2,%3}, [%4];"
                 : "=r"(r[0]), "=r"(r[1]), "=r"(r[2]), "=r"(r[3]) : "r"(a));
}
__device__ __forceinline__ void mma16816(float* c, const uint32_t* a, const uint32_t* b) {
    asm volatile(
        "mma.sync.aligned.m16n8k16.row.col.f32.bf16.bf16.f32 "
        "{%0,%1,%2,%3}, {%4,%5,%6,%7}, {%8,%9}, {%0,%1,%2,%3};"
        : "+f"(c[0]), "+f"(c[1]), "+f"(c[2]), "+f"(c[3])
        : "r"(a[0]), "r"(a[1]), "r"(a[2]), "r"(a[3]), "r"(b[0]), "r"(b[1]));
}
__device__ __forceinline__ void split2(float x0, float x1, uint32_t& hi, uint32_t& lo) {
    __nv_bfloat16 h0 = __float2bfloat16(x0);
    __nv_bfloat16 h1 = __float2bfloat16(x1);
    __nv_bfloat162 hv; hv.x = h0; hv.y = h1;
    __nv_bfloat162 lv;
    lv.x = __float2bfloat16(x0 - __bfloat162float(h0));
    lv.y = __float2bfloat16(x1 - __bfloat162float(h1));
    hi = *(uint32_t*)&hv;
    lo = *(uint32_t*)&lv;
}

// ---------------------------------------------------------------------------
// mma_gemm: C[M,N] = (Ah+Al)[M,K] @ (Bh+Bl)^T, B stored [N][K] bf16.
// bf16x3, CTA 128x128, BK=32, **4-stage** cp.async pipeline (only change vs
// the 1633us config: stage count 2 -> 4; tile layout identical).
// ---------------------------------------------------------------------------
#define RSB 40
#define TILE_B (128 * RSB * 2)             // 10240 B
#define BUF_B (4 * TILE_B)                 // 40960 B per stage
#define MMA_SMEM (4 * BUF_B)               // 163840 B

__global__ void __launch_bounds__(256, 1)
mma_gemm(const __nv_bfloat16* __restrict__ Ah, const __nv_bfloat16* __restrict__ Al,
         const __nv_bfloat16* __restrict__ Bh, const __nv_bfloat16* __restrict__ Bl,
         float* __restrict__ C, int ldc, int Kd) {
    extern __shared__ char smg[];
    const uint32_t sb = smem_u32(smg);
    const int tid = threadIdx.x, wid = tid >> 5, lane = tid & 31;
    const int warp_m = wid >> 2, warp_n = wid & 3;
    const int brow = blockIdx.y * 128, bcol = blockIdx.x * 128;

    float acc[4][4][4];
#pragma unroll
    for (int i = 0; i < 4; i++)
#pragma unroll
        for (int j = 0; j < 4; j++)
#pragma unroll
            for (int r = 0; r < 4; r++) acc[i][j][r] = 0.f;

    const int KT = Kd / 32;

    auto load_tile = [&](int kt, int buf) {
        const int k0 = kt * 32;
        const uint32_t bo = sb + buf * BUF_B;
#pragma unroll
        for (int s = tid; s < 512; s += 256) {
            const int row = s >> 2, seg = s & 3;
            const uint32_t so = (uint32_t)(row * 80 + seg * 16);
            const size_t ga = (size_t)(brow + row) * Kd + k0 + seg * 8;
            const size_t gb = (size_t)(bcol + row) * Kd + k0 + seg * 8;
            cp16(bo + so,              Ah + ga);
            cp16(bo + TILE_B + so,     Al + ga);
            cp16(bo + 2 * TILE_B + so, Bh + gb);
            cp16(bo + 3 * TILE_B + so, Bl + gb);
        }
        cp_commit();
    };

    // prologue: 3 tiles in flight
    load_tile(0, 0);
    load_tile(1, 1);
    load_tile(2, 2);

    for (int kt = 0; kt < KT; kt++) {
        const int cur = kt & 3;
        if (kt + 3 < KT) {
            load_tile(kt + 3, (kt + 3) & 3);
            asm volatile("cp.async.wait_group 3;" ::: "memory");
        } else {
            asm volatile("cp.async.wait_group 0;" ::: "memory");
        }
        __syncthreads();

        const uint32_t sA = sb + cur * BUF_B;
        const uint32_t sB = sA + 2 * TILE_B;
#pragma unroll
        for (int ks = 0; ks < 2; ks++) {
            uint32_t ah[4][4], al[4][4], bh[4][2], bl[4][2];
#pragma unroll
            for (int mt = 0; mt < 4; mt++) {
                uint32_t addr = sA + (uint32_t)((warp_m * 64 + mt * 16 + (lane & 15)) * 80
                                                + (ks * 16 + (lane >> 4) * 8) * 2);
                ldsm4(ah[mt], addr);
                ldsm4(al[mt], addr + TILE_B);
            }
#pragma unroll
            for (int p = 0; p < 2; p++) {
                uint32_t addr = sB + (uint32_t)((warp_n * 32 + p * 16 + (lane & 15)) * 80
                                                + ks * 32 + (lane >> 4) * 16);
                uint32_t r[4], q[4];
                ldsm4(r, addr);
                ldsm4(q, addr + TILE_B);
                bh[2 * p][0] = r[0]; bh[2 * p][1] = r[2];
                bh[2 * p + 1][0] = r[1]; bh[2 * p + 1][1] = r[3];
                bl[2 * p][0] = q[0]; bl[2 * p][1] = q[2];
                bl[2 * p + 1][0] = q[1]; bl[2 * p + 1][1] = q[3];
            }
#pragma unroll
            for (int mt = 0; mt < 4; mt++)
#pragma unroll
                for (int nt = 0; nt < 4; nt++) {
                    mma16816(acc[mt][nt], ah[mt], bh[nt]);
                    mma16816(acc[mt][nt], ah[mt], bl[nt]);
                    mma16816(acc[mt][nt], al[mt], bh[nt]);
                }
        }
        __syncthreads();
    }

#pragma unroll
    for (int mt = 0; mt < 4; mt++) {
#pragma unroll
        for (int nt = 0; nt < 4; nt++) {
            const int row0 = brow + warp_m * 64 + mt * 16 + (lane >> 2);
            const int col = bcol + warp_n * 32 + nt * 8 + (lane & 3) * 2;
            *(float2*)(C + (size_t)row0 * ldc + col) =
                make_float2(acc[mt][nt][0], acc[mt][nt][1]);
            *(float2*)(C + (size_t)(row0 + 8) * ldc + col) =
                make_float2(acc[mt][nt][2], acc[mt][nt][3]);
        }
    }
}

// ---------------------------------------------------------------------------
// bf16 hi/lo splits
// ---------------------------------------------------------------------------
__global__ void split_bf16(const float* __restrict__ src,
                           __nv_bfloat16* __restrict__ hi,
                           __nv_bfloat16* __restrict__ lo, int n) {
    int i = blockIdx.x * blockDim.x + threadIdx.x;
    if (i >= n) return;
    float x = src[i];
    __nv_bfloat16 h = __float2bfloat16(x);
    hi[i] = h;
    lo[i] = __float2bfloat16(x - __bfloat162float(h));
}

// strided split: src rows of `ldsrc`, cols [coff, coff+256) -> dense [row][256]
__global__ void split_bf16_strided(const float* __restrict__ src, int ldsrc, int coff,
                                   __nv_bfloat16* __restrict__ hi,
                                   __nv_bfloat16* __restrict__ lo, int n) {
    int i = blockIdx.x * blockDim.x + threadIdx.x;
    if (i >= n) return;
    int r = i >> 8, c = i & 255;
    float x = src[(size_t)r * ldsrc + coff + c];
    __nv_bfloat16 h = __float2bfloat16(x);
    hi[i] = h;
    lo[i] = __float2bfloat16(x - __bfloat162float(h));
}

__global__ void split_bf16_T(const float* __restrict__ W,
                             __nv_bfloat16* __restrict__ hi,
                             __nv_bfloat16* __restrict__ lo, int K, int N) {
    __shared__ float tile[32][33];
    int k0 = blockIdx.y * 32, n0 = blockIdx.x * 32;
    int tx = threadIdx.x, ty = threadIdx.y;
#pragma unroll
    for (int i = 0; i < 32; i += 8)
        tile[ty + i][tx] = W[(size_t)(k0 + ty + i) * N + n0 + tx];
    __syncthreads();
#pragma unroll
    for (int i = 0; i < 32; i += 8) {
        float x = tile[tx][ty + i];
        __nv_bfloat16 h = __float2bfloat16(x);
        size_t o = (size_t)(n0 + ty + i) * K + k0 + tx;
        hi[o] = h;
        lo[o] = __float2bfloat16(x - __bfloat162float(h));
    }
}

// ---------------------------------------------------------------------------
// RoPE table; RoPE apply + split (reads merged qkv fp32, writes dense q/k hi-lo)
// ---------------------------------------------------------------------------
__global__ void rope_table_kernel(const int* __restrict__ pos_ids) {
    int idx = blockIdx.x * blockDim.x + threadIdx.x;
    if (idx >= MROWS * 128) return;
    int i = idx & 127;
    int bs = idx >> 7;
    double freq = exp(-(double)i * 0.07195578415606392);
    double ang = (double)pos_ids[bs] * freq;
    double sd, cd;
    sincos(ang, &sd, &cd);
    g_rope[idx] = make_float2((float)cd, (float)sd);
}

__global__ void rope_apply_split() {
    int idx = blockIdx.x * blockDim.x + threadIdx.x;
    const int total = MROWS * 9 * 128;
    if (idx >= total) return;
    int i = idx & 127;
    int rest = idx >> 7;
    int h = rest % 9;
    int bs = rest / 9;
    float2 cs = g_rope[bs * 128 + i];

    const float* base;
    __nv_bfloat16 *dhi, *dlo;
    size_t o;
    if (h < 8) {
        base = g_qkv + (size_t)bs * QKVW + h * HDIM;
        o = (size_t)bs * (NH * HDIM) + h * HDIM;
        dhi = g_qhi; dlo = g_qlo;
    } else {
        base = g_qkv + (size_t)bs * QKVW + 2048;
        o = (size_t)bs * HDIM;
        dhi = g_khi; dlo = g_klo;
    }
    float x0 = base[i], x1 = base[i + 128];
    float y0 = x0 * cs.x - x1 * cs.y;
    float y1 = x1 * cs.x + x0 * cs.y;
    __nv_bfloat16 h0 = __float2bfloat16(y0);
    __nv_bfloat16 h1 = __float2bfloat16(y1);
    dhi[o + i] = h0;
    dlo[o + i] = __float2bfloat16(y0 - __bfloat162float(h0));
    dhi[o + i + 128] = h1;
    dlo[o + i + 128] = __float2bfloat16(y1 - __bfloat162float(h1));
}

// ---------------------------------------------------------------------------
// Tensor-core flash attention, register-resident softmax (exact 1633us R7
// structure: dense V buffers, fp32 g_ao output).
// ---------------------------------------------------------------------------
#define QS 264                 // bf16 row stride (528B, ldsm conflict-free)
#define O_QHI 0
#define O_QLO 67584
#define O_KHI 135168
#define O_KLO 168960
#define FLASH_SMEM 202752

__global__ void __launch_bounds__(256, 1)
flash_attn_tc(const float* __restrict__ mask) {
    extern __shared__ char smf[];
    const uint32_t sb = smem_u32(smf);
    const int tid = threadIdx.x, wid = tid >> 5, lane = tid & 31;
    const int q0 = blockIdx.x * 128;
    const int b = blockIdx.y >> 3, h = blockIdx.y & 7;

    // ---- Q tile (128 x 256 hi/lo) ----
    {
        const __nv_bfloat16* qh = g_qhi + (size_t)(b * SEQ + q0) * (NH * HDIM) + h * HDIM;
        const __nv_bfloat16* ql = g_qlo + (size_t)(b * SEQ + q0) * (NH * HDIM) + h * HDIM;
        for (int s = tid; s < 4096; s += 256) {
            int r = s >> 5, c = (s & 31) * 8;
            uint32_t d = (uint32_t)(r * QS + c) * 2;
            cp16(sb + O_QHI + d, qh + (size_t)r * (NH * HDIM) + c);
            cp16(sb + O_QLO + d, ql + (size_t)r * (NH * HDIM) + c);
        }
        cp_commit();
    }

    auto load_kv = [&](const __nv_bfloat16* hs, const __nv_bfloat16* ls) {
        for (int s = tid; s < 2048; s += 256) {
            int r = s >> 5, c = (s & 31) * 8;
            uint32_t d = (uint32_t)(r * QS + c) * 2;
            cp16(sb + O_KHI + d, hs + (size_t)r * HDIM + c);
            cp16(sb + O_KLO + d, ls + (size_t)r * HDIM + c);
        }
        cp_commit();
    };

    float o_acc[32][4];
#pragma unroll
    for (int i = 0; i < 32; i++)
#pragma unroll
        for (int r = 0; r < 4; r++) o_acc[i][r] = 0.f;
    float mval[2] = {-1e30f, -1e30f}, lval[2] = {0.f, 0.f};

    const uint32_t aBase = sb + O_QHI + (uint32_t)((wid * 16 + (lane & 15)) * QS) * 2
                           + (lane >> 4) * 16;
    const uint32_t bBase = sb + O_KHI + (uint32_t)((lane & 15) * QS) * 2 + (lane >> 4) * 16;
    const uint32_t vBase = sb + O_KHI + (uint32_t)((lane & 15) * QS) * 2
                           + (uint32_t)((lane >> 4) * 8) * 2;

    // first K tile
    load_kv(g_khi + (size_t)(b * SEQ) * HDIM, g_klo + (size_t)(b * SEQ) * HDIM);
    asm volatile("cp.async.wait_group 0;" ::: "memory");
    __syncthreads();

    for (int kt = 0; kt < 32; kt++) {
        const int k0 = kt * 64;

        // ---- scores: 16q x 64k over d=256 ----
        float c_[8][4];
#pragma unroll
        for (int i = 0; i < 8; i++)
#pragma unroll
            for (int r = 0; r < 4; r++) c_[i][r] = 0.f;

#pragma unroll
        for (int ks = 0; ks < 16; ks++) {
            uint32_t ah[4], al[4];
            ldsm4(ah, aBase + ks * 32);
            ldsm4(al, aBase + (O_QLO - O_QHI) + ks * 32);
#pragma unroll
            for (int p = 0; p < 4; p++) {
                uint32_t addr = bBase + (uint32_t)(p * 16 * QS) * 2 + ks * 32;
                uint32_t r[4], q[4];
                ldsm4(r, addr);
                ldsm4(q, addr + (O_KLO - O_KHI));
                uint32_t bh0[2] = {r[0], r[2]}, bh1[2] = {r[1], r[3]};
                uint32_t bl0[2] = {q[0], q[2]}, bl1[2] = {q[1], q[3]};
                mma16816(c_[2 * p], ah, bh0);
                mma16816(c_[2 * p], ah, bl0);
                mma16816(c_[2 * p], al, bh0);
                mma16816(c_[2 * p + 1], ah, bh1);
                mma16816(c_[2 * p + 1], ah, bl1);
                mma16816(c_[2 * p + 1], al, bh1);
            }
        }
        __syncthreads();

        // ---- prefetch V (overlaps softmax) ----
        load_kv(g_vhi + (size_t)(b * SEQ + k0) * HDIM,
                g_vlo + (size_t)(b * SEQ + k0) * HDIM);

        // ---- softmax in registers ----
        const float* mrow = mask + (size_t)b * SEQ * SEQ
                                 + (size_t)(q0 + wid * 16 + (lane >> 2)) * SEQ
                                 + k0 + (lane & 3) * 2;
#pragma unroll
        for (int h2 = 0; h2 < 2; h2++) {
            const float* mr = mrow + (size_t)(h2 * 8) * SEQ;
            float mx = -1e30f;
#pragma unroll
            for (int nt = 0; nt < 8; nt++) {
                float2 mk = *(const float2*)(mr + nt * 8);
                float v0 = c_[nt][2 * h2] * 0.0625f + mk.x;
                float v1 = c_[nt][2 * h2 + 1] * 0.0625f + mk.y;
                c_[nt][2 * h2] = v0;
                c_[nt][2 * h2 + 1] = v1;
                mx = fmaxf(mx, fmaxf(v0, v1));
            }
            mx = fmaxf(mx, __shfl_xor_sync(0xffffffffu, mx, 1));
            mx = fmaxf(mx, __shfl_xor_sync(0xffffffffu, mx, 2));
            float m_new = fmaxf(mval[h2], mx);
            float corr = __expf(mval[h2] - m_new);
            mval[h2] = m_new;
            float sum = 0.f;
#pragma unroll
            for (int nt = 0; nt < 8; nt++) {
                float p0 = __expf(c_[nt][2 * h2] - m_new);
                float p1 = __expf(c_[nt][2 * h2 + 1] - m_new);
                c_[nt][2 * h2] = p0;
                c_[nt][2 * h2 + 1] = p1;
                sum += p0 + p1;
            }
            sum += __shfl_xor_sync(0xffffffffu, sum, 1);
            sum += __shfl_xor_sync(0xffffffffu, sum, 2);
            lval[h2] = lval[h2] * corr + sum;
#pragma unroll
            for (int nt = 0; nt < 32; nt++) {
                o_acc[nt][2 * h2] *= corr;
                o_acc[nt][2 * h2 + 1] *= corr;
            }
        }

        // ---- pack P hi/lo fragments in registers ----
        uint32_t phi[4][4], plo[4][4];
#pragma unroll
        for (int kk = 0; kk < 4; kk++) {
#pragma unroll
            for (int j = 0; j < 4; j++) {
                int nt = 2 * kk + (j >> 1);
                int rb = (j & 1) * 2;
                split2(c_[nt][rb], c_[nt][rb + 1], phi[kk][j], plo[kk][j]);
            }
        }

        asm volatile("cp.async.wait_group 0;" ::: "memory");
        __syncthreads();

        // ---- PV: 16q x 256d over 64 keys ----
#pragma unroll
        for (int kk = 0; kk < 4; kk++) {
#pragma unroll
            for (int pr = 0; pr < 16; pr++) {
                uint32_t va = vBase + (uint32_t)(kk * 16 * QS) * 2 + pr * 32;
                uint32_t rh[4], rl[4];
                ldsm4t(rh, va);
                ldsm4t(rl, va + (O_KLO - O_KHI));
                uint32_t b0h[2] = {rh[0], rh[1]}, b1h[2] = {rh[2], rh[3]};
                uint32_t b0l[2] = {rl[0], rl[1]}, b1l[2] = {rl[2], rl[3]};
                mma16816(o_acc[2 * pr],     phi[kk], b0h);
                mma16816(o_acc[2 * pr],     phi[kk], b0l);
                mma16816(o_acc[2 * pr],     plo[kk], b0h);
                mma16816(o_acc[2 * pr + 1], phi[kk], b1h);
                mma16816(o_acc[2 * pr + 1], phi[kk], b1l);
                mma16816(o_acc[2 * pr + 1], plo[kk], b1h);
            }
        }
        __syncthreads();

        if (kt + 1 < 32) {
            load_kv(g_khi + (size_t)(b * SEQ + k0 + 64) * HDIM,
                    g_klo + (size_t)(b * SEQ + k0 + 64) * HDIM);
            asm volatile("cp.async.wait_group 0;" ::: "memory");
            __syncthreads();
        }
    }

    // ---- epilogue: normalize, write fp32 to g_ao ----
    float i0 = 1.0f / lval[0], i1 = 1.0f / lval[1];
    int r0 = q0 + wid * 16 + (lane >> 2);
    float* ao0 = g_ao + (size_t)(b * SEQ + r0) * (NH * HDIM) + h * HDIM + (lane & 3) * 2;
    float* ao1 = ao0 + (size_t)8 * (NH * HDIM);
#pragma unroll
    for (int nt = 0; nt < 32; nt++) {
        *(float2*)(ao0 + nt * 8) = make_float2(o_acc[nt][0] * i0, o_acc[nt][1] * i0);
        *(float2*)(ao1 + nt * 8) = make_float2(o_acc[nt][2] * i1, o_acc[nt][3] * i1);
    }
}

// ---------------------------------------------------------------------------
extern "C" void kernel_launch(void* const* d_in, const int* in_sizes, int n_in,
                              void* d_out, int out_size) {
    const float* hidden = (const float*)d_in[0];
    const float* mask   = (const float*)d_in[1];
    const int*   pos    = (const int*)d_in[2];
    const float* Wq     = (const float*)d_in[3];
    const float* Wk     = (const float*)d_in[4];
    const float* Wv     = (const float*)d_in[5];
    const float* Wo     = (const float*)d_in[6];
    float* out = (float*)d_out;

    float *qkvb, *aob;
    cudaGetSymbolAddress((void**)&qkvb, g_qkv);
    cudaGetSymbolAddress((void**)&aob, g_ao);
    __nv_bfloat16 *hh, *hl, *aoh, *aol, *wqkvh, *wqkvl, *oh, *ol, *vvh, *vvl;
    cudaGetSymbolAddress((void**)&hh, g_hid_hi);
    cudaGetSymbolAddress((void**)&hl, g_hid_lo);
    cudaGetSymbolAddress((void**)&aoh, g_ao_hi);
    cudaGetSymbolAddress((void**)&aol, g_ao_lo);
    cudaGetSymbolAddress((void**)&wqkvh, g_wqkv_hi);
    cudaGetSymbolAddress((void**)&wqkvl, g_wqkv_lo);
    cudaGetSymbolAddress((void**)&oh, g_wo_hi);
    cudaGetSymbolAddress((void**)&ol, g_wo_lo);
    cudaGetSymbolAddress((void**)&vvh, g_vhi);
    cudaGetSymbolAddress((void**)&vvl, g_vlo);

    cudaFuncSetAttribute(mma_gemm, cudaFuncAttributeMaxDynamicSharedMemorySize,
                         MMA_SMEM);
    cudaFuncSetAttribute(flash_attn_tc, cudaFuncAttributeMaxDynamicSharedMemorySize,
                         FLASH_SMEM);

    // 1: RoPE table (independent)
    int ttot = MROWS * 128;
    rope_table_kernel<<<(ttot + 255) / 256, 256>>>(pos);

    // 2: hidden split; 3-5: QKV weight splits (Wo split moved AFTER the QKV
    // GEMM so ncu -s 5 -c 1 profiles mma_gemm)
    int nh = MROWS * DMODEL;
    split_bf16<<<(nh + 255) / 256, 256>>>(hidden, hh, hl, nh);
    dim3 tb(32, 8);
    split_bf16_T<<<dim3(DMODEL / 32, DMODEL / 32), tb>>>(Wq, wqkvh, wqkvl, DMODEL, DMODEL);
    split_bf16_T<<<dim3(HDIM / 32, DMODEL / 32), tb>>>(
        Wk, wqkvh + (size_t)2048 * DMODEL, wqkvl + (size_t)2048 * DMODEL, DMODEL, HDIM);
    split_bf16_T<<<dim3(HDIM / 32, DMODEL / 32), tb>>>(
        Wv, wqkvh + (size_t)2304 * DMODEL, wqkvl + (size_t)2304 * DMODEL, DMODEL, HDIM);

    // 6: merged QKV projection (HMMA, 4-stage pipeline) -- profiled launch
    mma_gemm<<<dim3(QKVW / 128, MROWS / 128), 256, MMA_SMEM>>>(
        hh, hl, wqkvh, wqkvl, qkvb, QKVW, DMODEL);

    // 7: Wo weight split (independent of QKV gemm; reordered for profiling)
    split_bf16_T<<<dim3(DMODEL / 32, DMODEL / 32), tb>>>(Wo, oh, ol, DMODEL, DMODEL);

    // 8: RoPE + q/k split; 9: v split (dense)
    int rtot = MROWS * 9 * 128;
    rope_apply_split<<<(rtot + 255) / 256, 256>>>();
    int nv = MROWS * HDIM;
    split_bf16_strided<<<(nv + 255) / 256, 256>>>(qkvb, QKVW, 2304, vvh, vvl, nv);

    // 10: tensor-core flash attention (register softmax)
    dim3 gf(SEQ / 128, BATCH * NH);
    flash_attn_tc<<<gf, 256, FLASH_SMEM>>>(mask);

    // 11: ao split; 12: output projection
    split_bf16<<<(nh + 255) / 256, 256>>>(aob, aoh, aol, nh);
    mma_gemm<<<dim3(DMODEL / 128, MROWS / 128), 256, MMA_SMEM>>>(
        aoh, aol, oh, ol, out, DMODEL, DMODEL);
}

// round 11
// speedup vs baseline: 1.3388x; 1.3388x over previous
#include <cuda_runtime.h>
#include <cuda_bf16.h>
#include <cuda_fp16.h>
#include <math.h>
#include <stdint.h>

#define BATCH 2
#define SEQ 2048
#define DMODEL 2048
#define NH 8
#define HDIM 256
#define MROWS (BATCH * SEQ)          // 4096
#define QKVW 2560                    // merged qkv width (2048 q | 256 k | 256 v)

// ---------------- fp32 scratch ----------------
static __device__ float g_qkv[MROWS * QKVW];      // merged projection output
static __device__ float g_ao[MROWS * NH * HDIM];  // attention output (fp32)
static __device__ float2 g_rope[MROWS * 128];

// ---------------- bf16 split scratch (precision-critical chain) ----------------
static __device__ __nv_bfloat16 g_hid_hi[MROWS * DMODEL];
static __device__ __nv_bfloat16 g_hid_lo[MROWS * DMODEL];
static __device__ __nv_bfloat16 g_wqkv_hi[QKVW * DMODEL]; // [N][K]: q|k|v rows
static __device__ __nv_bfloat16 g_wqkv_lo[QKVW * DMODEL];
static __device__ __nv_bfloat16 g_qhi[MROWS * NH * HDIM];
static __device__ __nv_bfloat16 g_qlo[MROWS * NH * HDIM];
static __device__ __nv_bfloat16 g_khi[MROWS * HDIM];
static __device__ __nv_bfloat16 g_klo[MROWS * HDIM];
// ---------------- fp16 scratch (PV + Wo path) ----------------
static __device__ __half g_vh[MROWS * HDIM];       // V, fp16 single
static __device__ __half g_ao_h[MROWS * DMODEL];   // attention out, fp16 single
static __device__ __half g_wo_hi[DMODEL * DMODEL]; // Wo [N][K], fp16 hi/lo
static __device__ __half g_wo_lo[DMODEL * DMODEL];

// ---------------------------------------------------------------------------
// Warp-MMA helpers (baseline PTX, works under compute_103)
// ---------------------------------------------------------------------------
__device__ __forceinline__ uint32_t smem_u32(const void* p) {
    uint32_t a;
    asm("{ .reg .u64 t; cvta.to.shared.u64 t, %1; cvt.u32.u64 %0, t; }"
        : "=r"(a) : "l"(p));
    return a;
}
__device__ __forceinline__ void cp16(uint32_t s, const void* g) {
    asm volatile("cp.async.ca.shared.global [%0], [%1], 16;" :: "r"(s), "l"(g));
}
__device__ __forceinline__ void cp_commit() {
    asm volatile("cp.async.commit_group;" ::: "memory");
}
__device__ __forceinline__ void ldsm4(uint32_t* r, uint32_t a) {
    asm volatile("ldmatrix.sync.aligned.m8n8.x4.shared.b16 {%0,%1,%2,%3}, [%4];"
                 : "=r"(r[0]), "=r"(r[1]), "=r"(r[2]), "=r"(r[3]) : "r"(a));
}
__device__ __forceinline__ void ldsm4t(uint32_t* r, uint32_t a) {
    asm volatile("ldmatrix.sync.aligned.m8n8.x4.trans.shared.b16 {%0,%1,%2,%3}, [%4];"
                 : "=r"(r[0]), "=r"(r[1]), "=r"(r[2]), "=r"(r[3]) : "r"(a));
}
__device__ __forceinline__ void mma16816(float* c, const uint32_t* a, const uint32_t* b) {
    asm volatile(
        "mma.sync.aligned.m16n8k16.row.col.f32.bf16.bf16.f32 "
        "{%0,%1,%2,%3}, {%4,%5,%6,%7}, {%8,%9}, {%0,%1,%2,%3};"
        : "+f"(c[0]), "+f"(c[1]), "+f"(c[2]), "+f"(c[3])
        : "r"(a[0]), "r"(a[1]), "r"(a[2]), "r"(a[3]), "r"(b[0]), "r"(b[1]));
}
__device__ __forceinline__ void mma16816h(float* c, const uint32_t* a, const uint32_t* b) {
    asm volatile(
        "mma.sync.aligned.m16n8k16.row.col.f32.f16.f16.f32 "
        "{%0,%1,%2,%3}, {%4,%5,%6,%7}, {%8,%9}, {%0,%1,%2,%3};"
        : "+f"(c[0]), "+f"(c[1]), "+f"(c[2]), "+f"(c[3])
        : "r"(a[0]), "r"(a[1]), "r"(a[2]), "r"(a[3]), "r"(b[0]), "r"(b[1]));
}

// ---------------------------------------------------------------------------
// mma_gemm: bf16x3 compensated, CTA 128x128, BK=32, 2-stage (R7 = 1633us cfg)
// ---------------------------------------------------------------------------
#define RSB 40
#define TILE_B (128 * RSB * 2)
#define BUF_B (4 * TILE_B)
#define MMA_SMEM (2 * BUF_B)

__global__ void __launch_bounds__(256, 1)
mma_gemm(const __nv_bfloat16* __restrict__ Ah, const __nv_bfloat16* __restrict__ Al,
         const __nv_bfloat16* __restrict__ Bh, const __nv_bfloat16* __restrict__ Bl,
         float* __restrict__ C, int ldc, int Kd) {
    extern __shared__ char smg[];
    const uint32_t sb = smem_u32(smg);
    const int tid = threadIdx.x, wid = tid >> 5, lane = tid & 31;
    const int warp_m = wid >> 2, warp_n = wid & 3;
    const int brow = blockIdx.y * 128, bcol = blockIdx.x * 128;

    float acc[4][4][4];
#pragma unroll
    for (int i = 0; i < 4; i++)
#pragma unroll
        for (int j = 0; j < 4; j++)
#pragma unroll
            for (int r = 0; r < 4; r++) acc[i][j][r] = 0.f;

    const int KT = Kd / 32;

    auto load_tile = [&](int kt, int buf) {
        const int k0 = kt * 32;
        const uint32_t bo = sb + buf * BUF_B;
#pragma unroll
        for (int s = tid; s < 512; s += 256) {
            const int row = s >> 2, seg = s & 3;
            const uint32_t so = (uint32_t)(row * 80 + seg * 16);
            const size_t ga = (size_t)(brow + row) * Kd + k0 + seg * 8;
            const size_t gb = (size_t)(bcol + row) * Kd + k0 + seg * 8;
            cp16(bo + so,              Ah + ga);
            cp16(bo + TILE_B + so,     Al + ga);
            cp16(bo + 2 * TILE_B + so, Bh + gb);
            cp16(bo + 3 * TILE_B + so, Bl + gb);
        }
        cp_commit();
    };

    load_tile(0, 0);

    for (int kt = 0; kt < KT; kt++) {
        const int cur = kt & 1;
        if (kt + 1 < KT) {
            load_tile(kt + 1, cur ^ 1);
            asm volatile("cp.async.wait_group 1;" ::: "memory");
        } else {
            asm volatile("cp.async.wait_group 0;" ::: "memory");
        }
        __syncthreads();

        const uint32_t sA = sb + cur * BUF_B;
        const uint32_t sB = sA + 2 * TILE_B;
#pragma unroll
        for (int ks = 0; ks < 2; ks++) {
            uint32_t ah[4][4], al[4][4], bh[4][2], bl[4][2];
#pragma unroll
            for (int mt = 0; mt < 4; mt++) {
                uint32_t addr = sA + (uint32_t)((warp_m * 64 + mt * 16 + (lane & 15)) * 80
                                                + (ks * 16 + (lane >> 4) * 8) * 2);
                ldsm4(ah[mt], addr);
                ldsm4(al[mt], addr + TILE_B);
            }
#pragma unroll
            for (int p = 0; p < 2; p++) {
                uint32_t addr = sB + (uint32_t)((warp_n * 32 + p * 16 + (lane & 15)) * 80
                                                + ks * 32 + (lane >> 4) * 16);
                uint32_t r[4], q[4];
                ldsm4(r, addr);
                ldsm4(q, addr + TILE_B);
                bh[2 * p][0] = r[0]; bh[2 * p][1] = r[2];
                bh[2 * p + 1][0] = r[1]; bh[2 * p + 1][1] = r[3];
                bl[2 * p][0] = q[0]; bl[2 * p][1] = q[2];
                bl[2 * p + 1][0] = q[1]; bl[2 * p + 1][1] = q[3];
            }
#pragma unroll
            for (int mt = 0; mt < 4; mt++)
#pragma unroll
                for (int nt = 0; nt < 4; nt++) {
                    mma16816(acc[mt][nt], ah[mt], bh[nt]);
                    mma16816(acc[mt][nt], ah[mt], bl[nt]);
                    mma16816(acc[mt][nt], al[mt], bh[nt]);
                }
        }
        __syncthreads();
    }

#pragma unroll
    for (int mt = 0; mt < 4; mt++) {
#pragma unroll
        for (int nt = 0; nt < 4; nt++) {
            const int row0 = brow + warp_m * 64 + mt * 16 + (lane >> 2);
            const int col = bcol + warp_n * 32 + nt * 8 + (lane & 3) * 2;
            *(float2*)(C + (size_t)row0 * ldc + col) =
                make_float2(acc[mt][nt][0], acc[mt][nt][1]);
            *(float2*)(C + (size_t)(row0 + 8) * ldc + col) =
                make_float2(acc[mt][nt][2], acc[mt][nt][3]);
        }
    }
}

// ---------------------------------------------------------------------------
// mma_gemm_h2: C = A[M,K](fp16) @ (Bh+Bl)^T (fp16 x2), 2 MMAs per tile-step.
// Same tiling as mma_gemm; 3 smem arrays per stage.
// ---------------------------------------------------------------------------
#define BUF_H (3 * TILE_B)
#define MMA_H_SMEM (2 * BUF_H)

__global__ void __launch_bounds__(256, 1)
mma_gemm_h2(const __half* __restrict__ A,
            const __half* __restrict__ Bh, const __half* __restrict__ Bl,
            float* __restrict__ C, int ldc, int Kd) {
    extern __shared__ char smh[];
    const uint32_t sb = smem_u32(smh);
    const int tid = threadIdx.x, wid = tid >> 5, lane = tid & 31;
    const int warp_m = wid >> 2, warp_n = wid & 3;
    const int brow = blockIdx.y * 128, bcol = blockIdx.x * 128;

    float acc[4][4][4];
#pragma unroll
    for (int i = 0; i < 4; i++)
#pragma unroll
        for (int j = 0; j < 4; j++)
#pragma unroll
            for (int r = 0; r < 4; r++) acc[i][j][r] = 0.f;

    const int KT = Kd / 32;

    auto load_tile = [&](int kt, int buf) {
        const int k0 = kt * 32;
        const uint32_t bo = sb + buf * BUF_H;
#pragma unroll
        for (int s = tid; s < 512; s += 256) {
            const int row = s >> 2, seg = s & 3;
            const uint32_t so = (uint32_t)(row * 80 + seg * 16);
            const size_t ga = (size_t)(brow + row) * Kd + k0 + seg * 8;
            const size_t gb = (size_t)(bcol + row) * Kd + k0 + seg * 8;
            cp16(bo + so,              A + ga);
            cp16(bo + TILE_B + so,     Bh + gb);
            cp16(bo + 2 * TILE_B + so, Bl + gb);
        }
        cp_commit();
    };

    load_tile(0, 0);

    for (int kt = 0; kt < KT; kt++) {
        const int cur = kt & 1;
        if (kt + 1 < KT) {
            load_tile(kt + 1, cur ^ 1);
            asm volatile("cp.async.wait_group 1;" ::: "memory");
        } else {
            asm volatile("cp.async.wait_group 0;" ::: "memory");
        }
        __syncthreads();

        const uint32_t sA = sb + cur * BUF_H;
        const uint32_t sB = sA + TILE_B;
#pragma unroll
        for (int ks = 0; ks < 2; ks++) {
            uint32_t ah[4][4], bh[4][2], bl[4][2];
#pragma unroll
            for (int mt = 0; mt < 4; mt++) {
                uint32_t addr = sA + (uint32_t)((warp_m * 64 + mt * 16 + (lane & 15)) * 80
                                                + (ks * 16 + (lane >> 4) * 8) * 2);
                ldsm4(ah[mt], addr);
            }
#pragma unroll
            for (int p = 0; p < 2; p++) {
                uint32_t addr = sB + (uint32_t)((warp_n * 32 + p * 16 + (lane & 15)) * 80
                                                + ks * 32 + (lane >> 4) * 16);
                uint32_t r[4], q[4];
                ldsm4(r, addr);
                ldsm4(q, addr + TILE_B);
                bh[2 * p][0] = r[0]; bh[2 * p][1] = r[2];
                bh[2 * p + 1][0] = r[1]; bh[2 * p + 1][1] = r[3];
                bl[2 * p][0] = q[0]; bl[2 * p][1] = q[2];
                bl[2 * p + 1][0] = q[1]; bl[2 * p + 1][1] = q[3];
            }
#pragma unroll
            for (int mt = 0; mt < 4; mt++)
#pragma unroll
                for (int nt = 0; nt < 4; nt++) {
                    mma16816h(acc[mt][nt], ah[mt], bh[nt]);
                    mma16816h(acc[mt][nt], ah[mt], bl[nt]);
                }
        }
        __syncthreads();
    }

#pragma unroll
    for (int mt = 0; mt < 4; mt++) {
#pragma unroll
        for (int nt = 0; nt < 4; nt++) {
            const int row0 = brow + warp_m * 64 + mt * 16 + (lane >> 2);
            const int col = bcol + warp_n * 32 + nt * 8 + (lane & 3) * 2;
            *(float2*)(C + (size_t)row0 * ldc + col) =
                make_float2(acc[mt][nt][0], acc[mt][nt][1]);
            *(float2*)(C + (size_t)(row0 + 8) * ldc + col) =
                make_float2(acc[mt][nt][2], acc[mt][nt][3]);
        }
    }
}

// ---------------------------------------------------------------------------
// Split kernels
// ---------------------------------------------------------------------------
__global__ void split_bf16(const float* __restrict__ src,
                           __nv_bfloat16* __restrict__ hi,
                           __nv_bfloat16* __restrict__ lo, int n) {
    int i = blockIdx.x * blockDim.x + threadIdx.x;
    if (i >= n) return;
    float x = src[i];
    __nv_bfloat16 h = __float2bfloat16(x);
    hi[i] = h;
    lo[i] = __float2bfloat16(x - __bfloat162float(h));
}

__global__ void split_bf16_T(const float* __restrict__ W,
                             __nv_bfloat16* __restrict__ hi,
                             __nv_bfloat16* __restrict__ lo, int K, int N) {
    __shared__ float tile[32][33];
    int k0 = blockIdx.y * 32, n0 = blockIdx.x * 32;
    int tx = threadIdx.x, ty = threadIdx.y;
#pragma unroll
    for (int i = 0; i < 32; i += 8)
        tile[ty + i][tx] = W[(size_t)(k0 + ty + i) * N + n0 + tx];
    __syncthreads();
#pragma unroll
    for (int i = 0; i < 32; i += 8) {
        float x = tile[tx][ty + i];
        __nv_bfloat16 h = __float2bfloat16(x);
        size_t o = (size_t)(n0 + ty + i) * K + k0 + tx;
        hi[o] = h;
        lo[o] = __float2bfloat16(x - __bfloat162float(h));
    }
}

// fp16 hi/lo transpose split for Wo
__global__ void split_h_T(const float* __restrict__ W,
                          __half* __restrict__ hi, __half* __restrict__ lo,
                          int K, int N) {
    __shared__ float tile[32][33];
    int k0 = blockIdx.y * 32, n0 = blockIdx.x * 32;
    int tx = threadIdx.x, ty = threadIdx.y;
#pragma unroll
    for (int i = 0; i < 32; i += 8)
        tile[ty + i][tx] = W[(size_t)(k0 + ty + i) * N + n0 + tx];
    __syncthreads();
#pragma unroll
    for (int i = 0; i < 32; i += 8) {
        float x = tile[tx][ty + i];
        __half h = __float2half_rn(x);
        size_t o = (size_t)(n0 + ty + i) * K + k0 + tx;
        hi[o] = h;
        lo[o] = __float2half_rn(x - __half2float(h));
    }
}

// fp32 -> fp16 single (dense)
__global__ void cvt_h(const float* __restrict__ src, __half* __restrict__ dst, int n) {
    int i = blockIdx.x * blockDim.x + threadIdx.x;
    if (i >= n) return;
    dst[i] = __float2half_rn(src[i]);
}

// strided fp32 -> fp16 single: rows of ldsrc, cols [coff, coff+256)
__global__ void cvt_h_strided(const float* __restrict__ src, int ldsrc, int coff,
                              __half* __restrict__ dst, int n) {
    int i = blockIdx.x * blockDim.x + threadIdx.x;
    if (i >= n) return;
    int r = i >> 8, c = i & 255;
    dst[i] = __float2half_rn(src[(size_t)r * ldsrc + coff + c]);
}

// ---------------------------------------------------------------------------
// RoPE table; RoPE apply + bf16 split of q/k
// ---------------------------------------------------------------------------
__global__ void rope_table_kernel(const int* __restrict__ pos_ids) {
    int idx = blockIdx.x * blockDim.x + threadIdx.x;
    if (idx >= MROWS * 128) return;
    int i = idx & 127;
    int bs = idx >> 7;
    double freq = exp(-(double)i * 0.07195578415606392);
    double ang = (double)pos_ids[bs] * freq;
    double sd, cd;
    sincos(ang, &sd, &cd);
    g_rope[idx] = make_float2((float)cd, (float)sd);
}

__global__ void rope_apply_split() {
    int idx = blockIdx.x * blockDim.x + threadIdx.x;
    const int total = MROWS * 9 * 128;
    if (idx >= total) return;
    int i = idx & 127;
    int rest = idx >> 7;
    int h = rest % 9;
    int bs = rest / 9;
    float2 cs = g_rope[bs * 128 + i];

    const float* base;
    __nv_bfloat16 *dhi, *dlo;
    size_t o;
    if (h < 8) {
        base = g_qkv + (size_t)bs * QKVW + h * HDIM;
        o = (size_t)bs * (NH * HDIM) + h * HDIM;
        dhi = g_qhi; dlo = g_qlo;
    } else {
        base = g_qkv + (size_t)bs * QKVW + 2048;
        o = (size_t)bs * HDIM;
        dhi = g_khi; dlo = g_klo;
    }
    float x0 = base[i], x1 = base[i + 128];
    float y0 = x0 * cs.x - x1 * cs.y;
    float y1 = x1 * cs.x + x0 * cs.y;
    __nv_bfloat16 h0 = __float2bfloat16(y0);
    __nv_bfloat16 h1 = __float2bfloat16(y1);
    dhi[o + i] = h0;
    dlo[o + i] = __float2bfloat16(y0 - __bfloat162float(h0));
    dhi[o + i + 128] = h1;
    dlo[o + i + 128] = __float2bfloat16(y1 - __bfloat162float(h1));
}

// ---------------------------------------------------------------------------
// Tensor-core flash attention: scores bf16x3 (unchanged), PV fp16 single.
// ---------------------------------------------------------------------------
#define QS 264
#define O_QHI 0
#define O_QLO 67584
#define O_KHI 135168
#define O_KLO 168960
#define FLASH_SMEM 202752

__global__ void __launch_bounds__(256, 1)
flash_attn_tc(const float* __restrict__ mask) {
    extern __shared__ char smf[];
    const uint32_t sb = smem_u32(smf);
    const int tid = threadIdx.x, wid = tid >> 5, lane = tid & 31;
    const int q0 = blockIdx.x * 128;
    const int b = blockIdx.y >> 3, h = blockIdx.y & 7;

    // ---- Q tile (128 x 256 hi/lo bf16) ----
    {
        const __nv_bfloat16* qh = g_qhi + (size_t)(b * SEQ + q0) * (NH * HDIM) + h * HDIM;
        const __nv_bfloat16* ql = g_qlo + (size_t)(b * SEQ + q0) * (NH * HDIM) + h * HDIM;
        for (int s = tid; s < 4096; s += 256) {
            int r = s >> 5, c = (s & 31) * 8;
            uint32_t d = (uint32_t)(r * QS + c) * 2;
            cp16(sb + O_QHI + d, qh + (size_t)r * (NH * HDIM) + c);
            cp16(sb + O_QLO + d, ql + (size_t)r * (NH * HDIM) + c);
        }
        cp_commit();
    }

    auto load_k = [&](const __nv_bfloat16* hs, const __nv_bfloat16* ls) {
        for (int s = tid; s < 2048; s += 256) {
            int r = s >> 5, c = (s & 31) * 8;
            uint32_t d = (uint32_t)(r * QS + c) * 2;
            cp16(sb + O_KHI + d, hs + (size_t)r * HDIM + c);
            cp16(sb + O_KLO + d, ls + (size_t)r * HDIM + c);
        }
        cp_commit();
    };
    auto load_v = [&](const __half* vs) {
        for (int s = tid; s < 2048; s += 256) {
            int r = s >> 5, c = (s & 31) * 8;
            uint32_t d = (uint32_t)(r * QS + c) * 2;
            cp16(sb + O_KHI + d, vs + (size_t)r * HDIM + c);
        }
        cp_commit();
    };

    float o_acc[32][4];
#pragma unroll
    for (int i = 0; i < 32; i++)
#pragma unroll
        for (int r = 0; r < 4; r++) o_acc[i][r] = 0.f;
    float mval[2] = {-1e30f, -1e30f}, lval[2] = {0.f, 0.f};

    const uint32_t aBase = sb + O_QHI + (uint32_t)((wid * 16 + (lane & 15)) * QS) * 2
                           + (lane >> 4) * 16;
    const uint32_t bBase = sb + O_KHI + (uint32_t)((lane & 15) * QS) * 2 + (lane >> 4) * 16;
    const uint32_t vBase = sb + O_KHI + (uint32_t)((lane & 15) * QS) * 2
                           + (uint32_t)((lane >> 4) * 8) * 2;

    load_k(g_khi + (size_t)(b * SEQ) * HDIM, g_klo + (size_t)(b * SEQ) * HDIM);
    asm volatile("cp.async.wait_group 0;" ::: "memory");
    __syncthreads();

    for (int kt = 0; kt < 32; kt++) {
        const int k0 = kt * 64;

        // ---- scores: bf16x3, 16q x 64k over d=256 ----
        float c_[8][4];
#pragma unroll
        for (int i = 0; i < 8; i++)
#pragma unroll
            for (int r = 0; r < 4; r++) c_[i][r] = 0.f;

#pragma unroll
        for (int ks = 0; ks < 16; ks++) {
            uint32_t ah[4], al[4];
            ldsm4(ah, aBase + ks * 32);
            ldsm4(al, aBase + (O_QLO - O_QHI) + ks * 32);
#pragma unroll
            for (int p = 0; p < 4; p++) {
                uint32_t addr = bBase + (uint32_t)(p * 16 * QS) * 2 + ks * 32;
                uint32_t r[4], q[4];
                ldsm4(r, addr);
                ldsm4(q, addr + (O_KLO - O_KHI));
                uint32_t bh0[2] = {r[0], r[2]}, bh1[2] = {r[1], r[3]};
                uint32_t bl0[2] = {q[0], q[2]}, bl1[2] = {q[1], q[3]};
                mma16816(c_[2 * p], ah, bh0);
                mma16816(c_[2 * p], ah, bl0);
                mma16816(c_[2 * p], al, bh0);
                mma16816(c_[2 * p + 1], ah, bh1);
                mma16816(c_[2 * p + 1], ah, bl1);
                mma16816(c_[2 * p + 1], al, bh1);
            }
        }
        __syncthreads();

        // ---- prefetch V (fp16 single, overlaps softmax) ----
        load_v(g_vh + (size_t)(b * SEQ + k0) * HDIM);

        // ---- softmax in registers ----
        const float* mrow = mask + (size_t)b * SEQ * SEQ
                                 + (size_t)(q0 + wid * 16 + (lane >> 2)) * SEQ
                                 + k0 + (lane & 3) * 2;
#pragma unroll
        for (int h2 = 0; h2 < 2; h2++) {
            const float* mr = mrow + (size_t)(h2 * 8) * SEQ;
            float mx = -1e30f;
#pragma unroll
            for (int nt = 0; nt < 8; nt++) {
                float2 mk = *(const float2*)(mr + nt * 8);
                float v0 = c_[nt][2 * h2] * 0.0625f + mk.x;
                float v1 = c_[nt][2 * h2 + 1] * 0.0625f + mk.y;
                c_[nt][2 * h2] = v0;
                c_[nt][2 * h2 + 1] = v1;
                mx = fmaxf(mx, fmaxf(v0, v1));
            }
            mx = fmaxf(mx, __shfl_xor_sync(0xffffffffu, mx, 1));
            mx = fmaxf(mx, __shfl_xor_sync(0xffffffffu, mx, 2));
            float m_new = fmaxf(mval[h2], mx);
            float corr = __expf(mval[h2] - m_new);
            mval[h2] = m_new;
            float sum = 0.f;
#pragma unroll
            for (int nt = 0; nt < 8; nt++) {
                float p0 = __expf(c_[nt][2 * h2] - m_new);
                float p1 = __expf(c_[nt][2 * h2 + 1] - m_new);
                c_[nt][2 * h2] = p0;
                c_[nt][2 * h2 + 1] = p1;
                sum += p0 + p1;
            }
            sum += __shfl_xor_sync(0xffffffffu, sum, 1);
            sum += __shfl_xor_sync(0xffffffffu, sum, 2);
            lval[h2] = lval[h2] * corr + sum;
#pragma unroll
            for (int nt = 0; nt < 32; nt++) {
                o_acc[nt][2 * h2] *= corr;
                o_acc[nt][2 * h2 + 1] *= corr;
            }
        }

        // ---- pack P as fp16 single A-fragments ----
        uint32_t phi[4][4];
#pragma unroll
        for (int kk = 0; kk < 4; kk++) {
#pragma unroll
            for (int j = 0; j < 4; j++) {
                int nt = 2 * kk + (j >> 1);
                int rb = (j & 1) * 2;
                __half2 hv = __floats2half2_rn(c_[nt][rb], c_[nt][rb + 1]);
                phi[kk][j] = *(uint32_t*)&hv;
            }
        }

        asm volatile("cp.async.wait_group 0;" ::: "memory");
        __syncthreads();

        // ---- PV: fp16 single, 16q x 256d over 64 keys ----
#pragma unroll
        for (int kk = 0; kk < 4; kk++) {
#pragma unroll
            for (int pr = 0; pr < 16; pr++) {
                uint32_t va = vBase + (uint32_t)(kk * 16 * QS) * 2 + pr * 32;
                uint32_t rh[4];
                ldsm4t(rh, va);
                uint32_t b0h[2] = {rh[0], rh[1]}, b1h[2] = {rh[2], rh[3]};
                mma16816h(o_acc[2 * pr],     phi[kk], b0h);
                mma16816h(o_acc[2 * pr + 1], phi[kk], b1h);
            }
        }
        __syncthreads();

        if (kt + 1 < 32) {
            load_k(g_khi + (size_t)(b * SEQ + k0 + 64) * HDIM,
                   g_klo + (size_t)(b * SEQ + k0 + 64) * HDIM);
            asm volatile("cp.async.wait_group 0;" ::: "memory");
            __syncthreads();
        }
    }

    // ---- epilogue: normalize, write fp32 to g_ao ----
    float i0 = 1.0f / lval[0], i1 = 1.0f / lval[1];
    int r0 = q0 + wid * 16 + (lane >> 2);
    float* ao0 = g_ao + (size_t)(b * SEQ + r0) * (NH * HDIM) + h * HDIM + (lane & 3) * 2;
    float* ao1 = ao0 + (size_t)8 * (NH * HDIM);
#pragma unroll
    for (int nt = 0; nt < 32; nt++) {
        *(float2*)(ao0 + nt * 8) = make_float2(o_acc[nt][0] * i0, o_acc[nt][1] * i0);
        *(float2*)(ao1 + nt * 8) = make_float2(o_acc[nt][2] * i1, o_acc[nt][3] * i1);
    }
}

// ---------------------------------------------------------------------------
extern "C" void kernel_launch(void* const* d_in, const int* in_sizes, int n_in,
                              void* d_out, int out_size) {
    const float* hidden = (const float*)d_in[0];
    const float* mask   = (const float*)d_in[1];
    const int*   pos    = (const int*)d_in[2];
    const float* Wq     = (const float*)d_in[3];
    const float* Wk     = (const float*)d_in[4];
    const float* Wv     = (const float*)d_in[5];
    const float* Wo     = (const float*)d_in[6];
    float* out = (float*)d_out;

    float *qkvb, *aob;
    cudaGetSymbolAddress((void**)&qkvb, g_qkv);
    cudaGetSymbolAddress((void**)&aob, g_ao);
    __nv_bfloat16 *hh, *hl, *wqkvh, *wqkvl;
    cudaGetSymbolAddress((void**)&hh, g_hid_hi);
    cudaGetSymbolAddress((void**)&hl, g_hid_lo);
    cudaGetSymbolAddress((void**)&wqkvh, g_wqkv_hi);
    cudaGetSymbolAddress((void**)&wqkvl, g_wqkv_lo);
    __half *vh, *aohf, *woh, *wol;
    cudaGetSymbolAddress((void**)&vh, g_vh);
    cudaGetSymbolAddress((void**)&aohf, g_ao_h);
    cudaGetSymbolAddress((void**)&woh, g_wo_hi);
    cudaGetSymbolAddress((void**)&wol, g_wo_lo);

    cudaFuncSetAttribute(mma_gemm, cudaFuncAttributeMaxDynamicSharedMemorySize,
                         MMA_SMEM);
    cudaFuncSetAttribute(mma_gemm_h2, cudaFuncAttributeMaxDynamicSharedMemorySize,
                         MMA_H_SMEM);
    cudaFuncSetAttribute(flash_attn_tc, cudaFuncAttributeMaxDynamicSharedMemorySize,
                         FLASH_SMEM);

    // RoPE table (independent)
    int ttot = MROWS * 128;
    rope_table_kernel<<<(ttot + 255) / 256, 256>>>(pos);

    // Splits: hidden + weights
    int nh = MROWS * DMODEL;
    split_bf16<<<(nh + 255) / 256, 256>>>(hidden, hh, hl, nh);
    dim3 tb(32, 8);
    split_bf16_T<<<dim3(DMODEL / 32, DMODEL / 32), tb>>>(Wq, wqkvh, wqkvl, DMODEL, DMODEL);
    split_bf16_T<<<dim3(HDIM / 32, DMODEL / 32), tb>>>(
        Wk, wqkvh + (size_t)2048 * DMODEL, wqkvl + (size_t)2048 * DMODEL, DMODEL, HDIM);
    split_bf16_T<<<dim3(HDIM / 32, DMODEL / 32), tb>>>(
        Wv, wqkvh + (size_t)2304 * DMODEL, wqkvl + (size_t)2304 * DMODEL, DMODEL, HDIM);
    split_h_T<<<dim3(DMODEL / 32, DMODEL / 32), tb>>>(Wo, woh, wol, DMODEL, DMODEL);

    // Merged QKV projection (bf16x3)
    mma_gemm<<<dim3(QKVW / 128, MROWS / 128), 256, MMA_SMEM>>>(
        hh, hl, wqkvh, wqkvl, qkvb, QKVW, DMODEL);

    // RoPE + q/k bf16 split; V fp16 single
    int rtot = MROWS * 9 * 128;
    rope_apply_split<<<(rtot + 255) / 256, 256>>>();
    int nv = MROWS * HDIM;
    cvt_h_strided<<<(nv + 255) / 256, 256>>>(qkvb, QKVW, 2304, vh, nv);

    // Flash attention (scores bf16x3, PV fp16)
    dim3 gf(SEQ / 128, BATCH * NH);
    flash_attn_tc<<<gf, 256, FLASH_SMEM>>>(mask);

    // Output projection: ao fp16 single x Wo fp16 hi/lo
    cvt_h<<<(nh + 255) / 256, 256>>>(aob, aohf, nh);
    mma_gemm_h2<<<dim3(DMODEL / 128, MROWS / 128), 256, MMA_H_SMEM>>>(
        aohf, woh, wol, out, DMODEL, DMODEL);
}

// round 12
// speedup vs baseline: 1.6676x; 1.2456x over previous
#include <cuda_runtime.h>
#include <cuda_fp16.h>
#include <math.h>
#include <stdint.h>

#define BATCH 2
#define SEQ 2048
#define DMODEL 2048
#define NH 8
#define HDIM 256
#define MROWS (BATCH * SEQ)          // 4096
#define QKVW 2560                    // merged qkv width (2048 q | 256 k | 256 v)

// ---------------- fp32 scratch ----------------
static __device__ float g_qkv[MROWS * QKVW];      // merged projection output
static __device__ float g_ao[MROWS * NH * HDIM];  // attention output (fp32)
static __device__ float2 g_rope[MROWS * 128];

// ---------------- fp16 scratch ----------------
static __device__ __half g_hid_h[MROWS * DMODEL];    // hidden, fp16 single
static __device__ __half g_wqkv_hi[QKVW * DMODEL];   // [N][K] fp16 hi/lo
static __device__ __half g_wqkv_lo[QKVW * DMODEL];
static __device__ __half g_wo_hi[DMODEL * DMODEL];
static __device__ __half g_wo_lo[DMODEL * DMODEL];
static __device__ __half g_q_h[MROWS * NH * HDIM];   // post-RoPE Q, fp16 single
static __device__ __half g_k_hi[MROWS * HDIM];       // post-RoPE K, fp16 hi/lo
static __device__ __half g_k_lo[MROWS * HDIM];
static __device__ __half g_vh[MROWS * HDIM];         // V, fp16 single
static __device__ __half g_ao_h[MROWS * DMODEL];     // attention out, fp16 single

// ---------------------------------------------------------------------------
// Warp-MMA helpers (baseline PTX, works under compute_103)
// ---------------------------------------------------------------------------
__device__ __forceinline__ uint32_t smem_u32(const void* p) {
    uint32_t a;
    asm("{ .reg .u64 t; cvta.to.shared.u64 t, %1; cvt.u32.u64 %0, t; }"
        : "=r"(a) : "l"(p));
    return a;
}
__device__ __forceinline__ void cp16(uint32_t s, const void* g) {
    asm volatile("cp.async.ca.shared.global [%0], [%1], 16;" :: "r"(s), "l"(g));
}
__device__ __forceinline__ void cp_commit() {
    asm volatile("cp.async.commit_group;" ::: "memory");
}
__device__ __forceinline__ void ldsm4(uint32_t* r, uint32_t a) {
    asm volatile("ldmatrix.sync.aligned.m8n8.x4.shared.b16 {%0,%1,%2,%3}, [%4];"
                 : "=r"(r[0]), "=r"(r[1]), "=r"(r[2]), "=r"(r[3]) : "r"(a));
}
__device__ __forceinline__ void ldsm4t(uint32_t* r, uint32_t a) {
    asm volatile("ldmatrix.sync.aligned.m8n8.x4.trans.shared.b16 {%0,%1,%2,%3}, [%4];"
                 : "=r"(r[0]), "=r"(r[1]), "=r"(r[2]), "=r"(r[3]) : "r"(a));
}
__device__ __forceinline__ void mma16816h(float* c, const uint32_t* a, const uint32_t* b) {
    asm volatile(
        "mma.sync.aligned.m16n8k16.row.col.f32.f16.f16.f32 "
        "{%0,%1,%2,%3}, {%4,%5,%6,%7}, {%8,%9}, {%0,%1,%2,%3};"
        : "+f"(c[0]), "+f"(c[1]), "+f"(c[2]), "+f"(c[3])
        : "r"(a[0]), "r"(a[1]), "r"(a[2]), "r"(a[3]), "r"(b[0]), "r"(b[1]));
}

// ---------------------------------------------------------------------------
// mma_gemm_h2: C[M,N] = A[M,K](fp16) @ (Bh+Bl)^T (fp16 hi/lo), 2 MMAs/step.
// CTA 128x128, BK=32, 2-stage cp.async (measured-best base config).
// ---------------------------------------------------------------------------
#define RSB 40
#define TILE_B (128 * RSB * 2)
#define BUF_H (3 * TILE_B)
#define MMA_H_SMEM (2 * BUF_H)

__global__ void __launch_bounds__(256, 1)
mma_gemm_h2(const __half* __restrict__ A,
            const __half* __restrict__ Bh, const __half* __restrict__ Bl,
            float* __restrict__ C, int ldc, int Kd) {
    extern __shared__ char smh[];
    const uint32_t sb = smem_u32(smh);
    const int tid = threadIdx.x, wid = tid >> 5, lane = tid & 31;
    const int warp_m = wid >> 2, warp_n = wid & 3;
    const int brow = blockIdx.y * 128, bcol = blockIdx.x * 128;

    float acc[4][4][4];
#pragma unroll
    for (int i = 0; i < 4; i++)
#pragma unroll
        for (int j = 0; j < 4; j++)
#pragma unroll
            for (int r = 0; r < 4; r++) acc[i][j][r] = 0.f;

    const int KT = Kd / 32;

    auto load_tile = [&](int kt, int buf) {
        const int k0 = kt * 32;
        const uint32_t bo = sb + buf * BUF_H;
#pragma unroll
        for (int s = tid; s < 512; s += 256) {
            const int row = s >> 2, seg = s & 3;
            const uint32_t so = (uint32_t)(row * 80 + seg * 16);
            const size_t ga = (size_t)(brow + row) * Kd + k0 + seg * 8;
            const size_t gb = (size_t)(bcol + row) * Kd + k0 + seg * 8;
            cp16(bo + so,              A + ga);
            cp16(bo + TILE_B + so,     Bh + gb);
            cp16(bo + 2 * TILE_B + so, Bl + gb);
        }
        cp_commit();
    };

    load_tile(0, 0);

    for (int kt = 0; kt < KT; kt++) {
        const int cur = kt & 1;
        if (kt + 1 < KT) {
            load_tile(kt + 1, cur ^ 1);
            asm volatile("cp.async.wait_group 1;" ::: "memory");
        } else {
            asm volatile("cp.async.wait_group 0;" ::: "memory");
        }
        __syncthreads();

        const uint32_t sA = sb + cur * BUF_H;
        const uint32_t sB = sA + TILE_B;
#pragma unroll
        for (int ks = 0; ks < 2; ks++) {
            uint32_t ah[4][4], bh[4][2], bl[4][2];
#pragma unroll
            for (int mt = 0; mt < 4; mt++) {
                uint32_t addr = sA + (uint32_t)((warp_m * 64 + mt * 16 + (lane & 15)) * 80
                                                + (ks * 16 + (lane >> 4) * 8) * 2);
                ldsm4(ah[mt], addr);
            }
#pragma unroll
            for (int p = 0; p < 2; p++) {
                uint32_t addr = sB + (uint32_t)((warp_n * 32 + p * 16 + (lane & 15)) * 80
                                                + ks * 32 + (lane >> 4) * 16);
                uint32_t r[4], q[4];
                ldsm4(r, addr);
                ldsm4(q, addr + TILE_B);
                bh[2 * p][0] = r[0]; bh[2 * p][1] = r[2];
                bh[2 * p + 1][0] = r[1]; bh[2 * p + 1][1] = r[3];
                bl[2 * p][0] = q[0]; bl[2 * p][1] = q[2];
                bl[2 * p + 1][0] = q[1]; bl[2 * p + 1][1] = q[3];
            }
#pragma unroll
            for (int mt = 0; mt < 4; mt++)
#pragma unroll
                for (int nt = 0; nt < 4; nt++) {
                    mma16816h(acc[mt][nt], ah[mt], bh[nt]);
                    mma16816h(acc[mt][nt], ah[mt], bl[nt]);
                }
        }
        __syncthreads();
    }

#pragma unroll
    for (int mt = 0; mt < 4; mt++) {
#pragma unroll
        for (int nt = 0; nt < 4; nt++) {
            const int row0 = brow + warp_m * 64 + mt * 16 + (lane >> 2);
            const int col = bcol + warp_n * 32 + nt * 8 + (lane & 3) * 2;
            *(float2*)(C + (size_t)row0 * ldc + col) =
                make_float2(acc[mt][nt][0], acc[mt][nt][1]);
            *(float2*)(C + (size_t)(row0 + 8) * ldc + col) =
                make_float2(acc[mt][nt][2], acc[mt][nt][3]);
        }
    }
}

// ---------------------------------------------------------------------------
// Conversion / split kernels
// ---------------------------------------------------------------------------
__global__ void cvt_h(const float* __restrict__ src, __half* __restrict__ dst, int n) {
    int i = blockIdx.x * blockDim.x + threadIdx.x;
    if (i >= n) return;
    dst[i] = __float2half_rn(src[i]);
}

__global__ void cvt_h_strided(const float* __restrict__ src, int ldsrc, int coff,
                              __half* __restrict__ dst, int n) {
    int i = blockIdx.x * blockDim.x + threadIdx.x;
    if (i >= n) return;
    int r = i >> 8, c = i & 255;
    dst[i] = __float2half_rn(src[(size_t)r * ldsrc + coff + c]);
}

// fp16 hi/lo transpose split: W[K][N] -> hi/lo [N][K]
__global__ void split_h_T(const float* __restrict__ W,
                          __half* __restrict__ hi, __half* __restrict__ lo,
                          int K, int N) {
    __shared__ float tile[32][33];
    int k0 = blockIdx.y * 32, n0 = blockIdx.x * 32;
    int tx = threadIdx.x, ty = threadIdx.y;
#pragma unroll
    for (int i = 0; i < 32; i += 8)
        tile[ty + i][tx] = W[(size_t)(k0 + ty + i) * N + n0 + tx];
    __syncthreads();
#pragma unroll
    for (int i = 0; i < 32; i += 8) {
        float x = tile[tx][ty + i];
        __half h = __float2half_rn(x);
        size_t o = (size_t)(n0 + ty + i) * K + k0 + tx;
        hi[o] = h;
        lo[o] = __float2half_rn(x - __half2float(h));
    }
}

// ---------------------------------------------------------------------------
// RoPE table; RoPE apply: Q -> fp16 single, K -> fp16 hi/lo
// ---------------------------------------------------------------------------
__global__ void rope_table_kernel(const int* __restrict__ pos_ids) {
    int idx = blockIdx.x * blockDim.x + threadIdx.x;
    if (idx >= MROWS * 128) return;
    int i = idx & 127;
    int bs = idx >> 7;
    double freq = exp(-(double)i * 0.07195578415606392);
    double ang = (double)pos_ids[bs] * freq;
    double sd, cd;
    sincos(ang, &sd, &cd);
    g_rope[idx] = make_float2((float)cd, (float)sd);
}

__global__ void rope_apply_split() {
    int idx = blockIdx.x * blockDim.x + threadIdx.x;
    const int total = MROWS * 9 * 128;
    if (idx >= total) return;
    int i = idx & 127;
    int rest = idx >> 7;
    int h = rest % 9;
    int bs = rest / 9;
    float2 cs = g_rope[bs * 128 + i];

    if (h < 8) {
        const float* base = g_qkv + (size_t)bs * QKVW + h * HDIM;
        size_t o = (size_t)bs * (NH * HDIM) + h * HDIM;
        float x0 = base[i], x1 = base[i + 128];
        float y0 = x0 * cs.x - x1 * cs.y;
        float y1 = x1 * cs.x + x0 * cs.y;
        g_q_h[o + i] = __float2half_rn(y0);
        g_q_h[o + i + 128] = __float2half_rn(y1);
    } else {
        const float* base = g_qkv + (size_t)bs * QKVW + 2048;
        size_t o = (size_t)bs * HDIM;
        float x0 = base[i], x1 = base[i + 128];
        float y0 = x0 * cs.x - x1 * cs.y;
        float y1 = x1 * cs.x + x0 * cs.y;
        __half h0 = __float2half_rn(y0);
        __half h1 = __float2half_rn(y1);
        g_k_hi[o + i] = h0;
        g_k_lo[o + i] = __float2half_rn(y0 - __half2float(h0));
        g_k_hi[o + i + 128] = h1;
        g_k_lo[o + i + 128] = __float2half_rn(y1 - __half2float(h1));
    }
}

// ---------------------------------------------------------------------------
// Tensor-core flash attention.
// Scores: Q fp16 single x K fp16 hi/lo (2 MMAs). PV: fp16 single (2 MMAs/16d).
// Register-resident softmax, 128q CTA, 8 warps x 16q.
// ---------------------------------------------------------------------------
#define QS 264                 // fp16 row stride (528B, ldsm conflict-free)
#define O_Q   0                // 128 x QS fp16 = 67584 B
#define O_KHI 67584            // 64 x QS fp16 = 33792 B
#define O_KLO 101376           // 33792 B
#define FLASH_SMEM 135168

__global__ void __launch_bounds__(256, 1)
flash_attn_tc(const float* __restrict__ mask) {
    extern __shared__ char smf[];
    const uint32_t sb = smem_u32(smf);
    const int tid = threadIdx.x, wid = tid >> 5, lane = tid & 31;
    const int q0 = blockIdx.x * 128;
    const int b = blockIdx.y >> 3, h = blockIdx.y & 7;

    // ---- Q tile (128 x 256 fp16 single) ----
    {
        const __half* qh = g_q_h + (size_t)(b * SEQ + q0) * (NH * HDIM) + h * HDIM;
        for (int s = tid; s < 4096; s += 256) {
            int r = s >> 5, c = (s & 31) * 8;
            cp16(sb + O_Q + (uint32_t)(r * QS + c) * 2, qh + (size_t)r * (NH * HDIM) + c);
        }
        cp_commit();
    }

    auto load_k = [&](const __half* hs, const __half* ls) {
        for (int s = tid; s < 2048; s += 256) {
            int r = s >> 5, c = (s & 31) * 8;
            uint32_t d = (uint32_t)(r * QS + c) * 2;
            cp16(sb + O_KHI + d, hs + (size_t)r * HDIM + c);
            cp16(sb + O_KLO + d, ls + (size_t)r * HDIM + c);
        }
        cp_commit();
    };
    auto load_v = [&](const __half* vs) {
        for (int s = tid; s < 2048; s += 256) {
            int r = s >> 5, c = (s & 31) * 8;
            cp16(sb + O_KHI + (uint32_t)(r * QS + c) * 2, vs + (size_t)r * HDIM + c);
        }
        cp_commit();
    };

    float o_acc[32][4];
#pragma unroll
    for (int i = 0; i < 32; i++)
#pragma unroll
        for (int r = 0; r < 4; r++) o_acc[i][r] = 0.f;
    float mval[2] = {-1e30f, -1e30f}, lval[2] = {0.f, 0.f};

    const uint32_t aBase = sb + O_Q + (uint32_t)((wid * 16 + (lane & 15)) * QS) * 2
                           + (lane >> 4) * 16;
    const uint32_t bBase = sb + O_KHI + (uint32_t)((lane & 15) * QS) * 2 + (lane >> 4) * 16;
    const uint32_t vBase = sb + O_KHI + (uint32_t)((lane & 15) * QS) * 2
                           + (uint32_t)((lane >> 4) * 8) * 2;

    load_k(g_k_hi + (size_t)(b * SEQ) * HDIM, g_k_lo + (size_t)(b * SEQ) * HDIM);
    asm volatile("cp.async.wait_group 0;" ::: "memory");
    __syncthreads();

    for (int kt = 0; kt < 32; kt++) {
        const int k0 = kt * 64;

        // ---- scores: Q single x K hi/lo, 16q x 64k over d=256 ----
        float c_[8][4];
#pragma unroll
        for (int i = 0; i < 8; i++)
#pragma unroll
            for (int r = 0; r < 4; r++) c_[i][r] = 0.f;

#pragma unroll
        for (int ks = 0; ks < 16; ks++) {
            uint32_t ah[4];
            ldsm4(ah, aBase + ks * 32);
#pragma unroll
            for (int p = 0; p < 4; p++) {
                uint32_t addr = bBase + (uint32_t)(p * 16 * QS) * 2 + ks * 32;
                uint32_t r[4], q[4];
                ldsm4(r, addr);
                ldsm4(q, addr + (O_KLO - O_KHI));
                uint32_t bh0[2] = {r[0], r[2]}, bh1[2] = {r[1], r[3]};
                uint32_t bl0[2] = {q[0], q[2]}, bl1[2] = {q[1], q[3]};
                mma16816h(c_[2 * p], ah, bh0);
                mma16816h(c_[2 * p], ah, bl0);
                mma16816h(c_[2 * p + 1], ah, bh1);
                mma16816h(c_[2 * p + 1], ah, bl1);
            }
        }
        __syncthreads();

        // ---- prefetch V (overlaps softmax) ----
        load_v(g_vh + (size_t)(b * SEQ + k0) * HDIM);

        // ---- softmax in registers ----
        const float* mrow = mask + (size_t)b * SEQ * SEQ
                                 + (size_t)(q0 + wid * 16 + (lane >> 2)) * SEQ
                                 + k0 + (lane & 3) * 2;
#pragma unroll
        for (int h2 = 0; h2 < 2; h2++) {
            const float* mr = mrow + (size_t)(h2 * 8) * SEQ;
            float mx = -1e30f;
#pragma unroll
            for (int nt = 0; nt < 8; nt++) {
                float2 mk = *(const float2*)(mr + nt * 8);
                float v0 = c_[nt][2 * h2] * 0.0625f + mk.x;
                float v1 = c_[nt][2 * h2 + 1] * 0.0625f + mk.y;
                c_[nt][2 * h2] = v0;
                c_[nt][2 * h2 + 1] = v1;
                mx = fmaxf(mx, fmaxf(v0, v1));
            }
            mx = fmaxf(mx, __shfl_xor_sync(0xffffffffu, mx, 1));
            mx = fmaxf(mx, __shfl_xor_sync(0xffffffffu, mx, 2));
            float m_new = fmaxf(mval[h2], mx);
            float corr = __expf(mval[h2] - m_new);
            mval[h2] = m_new;
            float sum = 0.f;
#pragma unroll
            for (int nt = 0; nt < 8; nt++) {
                float p0 = __expf(c_[nt][2 * h2] - m_new);
                float p1 = __expf(c_[nt][2 * h2 + 1] - m_new);
                c_[nt][2 * h2] = p0;
                c_[nt][2 * h2 + 1] = p1;
                sum += p0 + p1;
            }
            sum += __shfl_xor_sync(0xffffffffu, sum, 1);
            sum += __shfl_xor_sync(0xffffffffu, sum, 2);
            lval[h2] = lval[h2] * corr + sum;
#pragma unroll
            for (int nt = 0; nt < 32; nt++) {
                o_acc[nt][2 * h2] *= corr;
                o_acc[nt][2 * h2 + 1] *= corr;
            }
        }

        // ---- pack P as fp16 A-fragments ----
        uint32_t phi[4][4];
#pragma unroll
        for (int kk = 0; kk < 4; kk++) {
#pragma unroll
            for (int j = 0; j < 4; j++) {
                int nt = 2 * kk + (j >> 1);
                int rb = (j & 1) * 2;
                __half2 hv = __floats2half2_rn(c_[nt][rb], c_[nt][rb + 1]);
                phi[kk][j] = *(uint32_t*)&hv;
            }
        }

        asm volatile("cp.async.wait_group 0;" ::: "memory");
        __syncthreads();

        // ---- PV: fp16, 16q x 256d over 64 keys ----
#pragma unroll
        for (int kk = 0; kk < 4; kk++) {
#pragma unroll
            for (int pr = 0; pr < 16; pr++) {
                uint32_t va = vBase + (uint32_t)(kk * 16 * QS) * 2 + pr * 32;
                uint32_t rh[4];
                ldsm4t(rh, va);
                uint32_t b0h[2] = {rh[0], rh[1]}, b1h[2] = {rh[2], rh[3]};
                mma16816h(o_acc[2 * pr],     phi[kk], b0h);
                mma16816h(o_acc[2 * pr + 1], phi[kk], b1h);
            }
        }
        __syncthreads();

        if (kt + 1 < 32) {
            load_k(g_k_hi + (size_t)(b * SEQ + k0 + 64) * HDIM,
                   g_k_lo + (size_t)(b * SEQ + k0 + 64) * HDIM);
            asm volatile("cp.async.wait_group 0;" ::: "memory");
            __syncthreads();
        }
    }

    // ---- epilogue: normalize, write fp32 to g_ao ----
    float i0 = 1.0f / lval[0], i1 = 1.0f / lval[1];
    int r0 = q0 + wid * 16 + (lane >> 2);
    float* ao0 = g_ao + (size_t)(b * SEQ + r0) * (NH * HDIM) + h * HDIM + (lane & 3) * 2;
    float* ao1 = ao0 + (size_t)8 * (NH * HDIM);
#pragma unroll
    for (int nt = 0; nt < 32; nt++) {
        *(float2*)(ao0 + nt * 8) = make_float2(o_acc[nt][0] * i0, o_acc[nt][1] * i0);
        *(float2*)(ao1 + nt * 8) = make_float2(o_acc[nt][2] * i1, o_acc[nt][3] * i1);
    }
}

// ---------------------------------------------------------------------------
extern "C" void kernel_launch(void* const* d_in, const int* in_sizes, int n_in,
                              void* d_out, int out_size) {
    const float* hidden = (const float*)d_in[0];
    const float* mask   = (const float*)d_in[1];
    const int*   pos    = (const int*)d_in[2];
    const float* Wq     = (const float*)d_in[3];
    const float* Wk     = (const float*)d_in[4];
    const float* Wv     = (const float*)d_in[5];
    const float* Wo     = (const float*)d_in[6];
    float* out = (float*)d_out;

    float *qkvb, *aob;
    cudaGetSymbolAddress((void**)&qkvb, g_qkv);
    cudaGetSymbolAddress((void**)&aob, g_ao);
    __half *hidh, *wqkvh, *wqkvl, *woh, *wol, *vh, *aohf;
    cudaGetSymbolAddress((void**)&hidh, g_hid_h);
    cudaGetSymbolAddress((void**)&wqkvh, g_wqkv_hi);
    cudaGetSymbolAddress((void**)&wqkvl, g_wqkv_lo);
    cudaGetSymbolAddress((void**)&woh, g_wo_hi);
    cudaGetSymbolAddress((void**)&wol, g_wo_lo);
    cudaGetSymbolAddress((void**)&vh, g_vh);
    cudaGetSymbolAddress((void**)&aohf, g_ao_h);

    cudaFuncSetAttribute(mma_gemm_h2, cudaFuncAttributeMaxDynamicSharedMemorySize,
                         MMA_H_SMEM);
    cudaFuncSetAttribute(flash_attn_tc, cudaFuncAttributeMaxDynamicSharedMemorySize,
                         FLASH_SMEM);

    // RoPE table (independent)
    int ttot = MROWS * 128;
    rope_table_kernel<<<(ttot + 255) / 256, 256>>>(pos);

    // hidden -> fp16 single; weights -> fp16 hi/lo transposed [N][K]
    int nh = MROWS * DMODEL;
    cvt_h<<<(nh + 255) / 256, 256>>>(hidden, hidh, nh);
    dim3 tb(32, 8);
    split_h_T<<<dim3(DMODEL / 32, DMODEL / 32), tb>>>(Wq, wqkvh, wqkvl, DMODEL, DMODEL);
    split_h_T<<<dim3(HDIM / 32, DMODEL / 32), tb>>>(
        Wk, wqkvh + (size_t)2048 * DMODEL, wqkvl + (size_t)2048 * DMODEL, DMODEL, HDIM);
    split_h_T<<<dim3(HDIM / 32, DMODEL / 32), tb>>>(
        Wv, wqkvh + (size_t)2304 * DMODEL, wqkvl + (size_t)2304 * DMODEL, DMODEL, HDIM);
    split_h_T<<<dim3(DMODEL / 32, DMODEL / 32), tb>>>(Wo, woh, wol, DMODEL, DMODEL);

    // Merged QKV projection (fp16 single x fp16 hi/lo)
    mma_gemm_h2<<<dim3(QKVW / 128, MROWS / 128), 256, MMA_H_SMEM>>>(
        hidh, wqkvh, wqkvl, qkvb, QKVW, DMODEL);

    // RoPE: Q fp16 single, K fp16 hi/lo; V fp16 single
    int rtot = MROWS * 9 * 128;
    rope_apply_split<<<(rtot + 255) / 256, 256>>>();
    int nv = MROWS * HDIM;
    cvt_h_strided<<<(nv + 255) / 256, 256>>>(qkvb, QKVW, 2304, vh, nv);

    // Flash attention (scores fp16 Qx(Khi+Klo), PV fp16)
    dim3 gf(SEQ / 128, BATCH * NH);
    flash_attn_tc<<<gf, 256, FLASH_SMEM>>>(mask);

    // Output projection: ao fp16 single x Wo fp16 hi/lo
    cvt_h<<<(nh + 255) / 256, 256>>>(aob, aohf, nh);
    mma_gemm_h2<<<dim3(DMODEL / 128, MROWS / 128), 256, MMA_H_SMEM>>>(
        aohf, woh, wol, out, DMODEL, DMODEL);
}